// round 2
// baseline (speedup 1.0000x reference)
#include <cuda_runtime.h>
#include <cstdint>

// ---------------------------------------------------------------------------
// GCNEncoder: 2-layer GCN
//   h1 = relu( Dinv (A+I) Dinv (x @ W1) + b1 )
//   out =      Dinv (A+I) Dinv (h1 @ W2) + b2
// N = 100000 nodes, E = 1600000 edges, 128 channels everywhere.
// ---------------------------------------------------------------------------

#define MAX_N 100000
#define MAX_E 1600000
#define CH 128

// Scratch (allocation-free rule: __device__ globals), 16B-aligned for float4.
__device__ alignas(16) float g_h[(size_t)MAX_N * CH];    // per-layer GEMM output
__device__ alignas(16) float g_agg[(size_t)MAX_N * CH];  // layer-1 aggregation buffer
__device__ float g_dinv[MAX_N];
__device__ int   g_deg[MAX_N];
__device__ int   g_idx[2 * MAX_E];     // converted int32 src/dst
__device__ float g_coef[MAX_E];        // per-edge dinv[src]*dinv[dst]
__device__ unsigned int g_or_hi;       // dtype-detection accumulator

// ---------------------------------------------------------------------------
// Edge-index dtype detection + conversion.
// The harness may deliver edge_index as int64 or int32. For int64 values in
// [0, N) the high 32-bit word of every element is 0; for int32 random values
// the odd-indexed words are ~never all zero. Deterministic per input.
// ---------------------------------------------------------------------------
__global__ void detect_zero_kernel() {
    if (threadIdx.x == 0 && blockIdx.x == 0) g_or_hi = 0u;
}

__global__ void detect_kernel(const unsigned int* __restrict__ w, int nwords) {
    // Examine odd words among the first min(2048, nwords) 32-bit words.
    unsigned int v = 0;
    for (int i = threadIdx.x; i < 1024; i += blockDim.x) {
        int idx = 2 * i + 1;
        if (idx < nwords) v |= w[idx];
    }
    // reduce within warp then atomically into global
    for (int off = 16; off > 0; off >>= 1)
        v |= __shfl_down_sync(0xFFFFFFFFu, v, off);
    if ((threadIdx.x & 31) == 0 && v) atomicOr(&g_or_hi, v);
}

__global__ void convert_kernel(const void* __restrict__ ei, int total) {
    int i = blockIdx.x * blockDim.x + threadIdx.x;
    if (i >= total) return;
    int v;
    if (g_or_hi == 0u) {
        v = (int)((const long long*)ei)[i];   // int64 input
    } else {
        v = ((const int*)ei)[i];              // int32 input
    }
    g_idx[i] = v;
}

// ---------------------------------------------------------------------------
// Degree + dinv + per-edge coefficient
// ---------------------------------------------------------------------------
__global__ void zero_deg_kernel(int n) {
    int i = blockIdx.x * blockDim.x + threadIdx.x;
    if (i < n) g_deg[i] = 0;
}

__global__ void deg_kernel(int E) {
    int i = blockIdx.x * blockDim.x + threadIdx.x;
    if (i < E) atomicAdd(&g_deg[g_idx[E + i]], 1);
}

__global__ void dinv_kernel(int n) {
    int i = blockIdx.x * blockDim.x + threadIdx.x;
    if (i < n) g_dinv[i] = rsqrtf((float)g_deg[i] + 1.0f);
}

__global__ void coef_kernel(int E) {
    int i = blockIdx.x * blockDim.x + threadIdx.x;
    if (i < E) g_coef[i] = g_dinv[g_idx[i]] * g_dinv[g_idx[E + i]];
}

// ---------------------------------------------------------------------------
// GEMM: C[n,128] = act(A[n,128]) @ W[128,128]
// 128x128 tile per block, 256 threads, 8x8 register blocking, BK=16.
// ---------------------------------------------------------------------------
template <bool RELU>
__global__ void __launch_bounds__(256)
gemm128_kernel(const float* __restrict__ A, const float* __restrict__ W,
               float* __restrict__ C, int n) {
    __shared__ float As[16][CH + 4];   // transposed A tile: As[k][row]
    __shared__ float Ws[16][CH];

    const int block_row = blockIdx.x * 128;
    const int tid = threadIdx.x;
    const int tx = tid & 15;           // 0..15 -> 8 output cols each
    const int ty = tid >> 4;           // 0..15 -> 8 output rows each

    float acc[8][8];
#pragma unroll
    for (int i = 0; i < 8; i++)
#pragma unroll
        for (int j = 0; j < 8; j++) acc[i][j] = 0.0f;

    for (int k0 = 0; k0 < CH; k0 += 16) {
#pragma unroll
        for (int i = 0; i < 8; i++) {
            int idx = tid + i * 256;         // 0..2047
            int r = idx >> 4;                // 0..127
            int c = idx & 15;                // 0..15
            int gr = block_row + r;
            float v = 0.0f;
            if (gr < n) {
                v = A[(size_t)gr * CH + k0 + c];
                if (RELU) v = fmaxf(v, 0.0f);
            }
            As[c][r] = v;
        }
#pragma unroll
        for (int i = 0; i < 8; i++) {
            int idx = tid + i * 256;
            int r = idx >> 7;                // 0..15
            int c = idx & 127;               // 0..127
            Ws[r][c] = W[(k0 + r) * CH + c];
        }
        __syncthreads();

#pragma unroll
        for (int k = 0; k < 16; k++) {
            float a[8], b[8];
#pragma unroll
            for (int i = 0; i < 8; i++) a[i] = As[k][ty * 8 + i];
#pragma unroll
            for (int j = 0; j < 8; j++) b[j] = Ws[k][tx * 8 + j];
#pragma unroll
            for (int i = 0; i < 8; i++)
#pragma unroll
                for (int j = 0; j < 8; j++) acc[i][j] = fmaf(a[i], b[j], acc[i][j]);
        }
        __syncthreads();
    }

#pragma unroll
    for (int i = 0; i < 8; i++) {
        int gr = block_row + ty * 8 + i;
        if (gr < n) {
            float4* out = (float4*)(C + (size_t)gr * CH + tx * 8);
            out[0] = make_float4(acc[i][0], acc[i][1], acc[i][2], acc[i][3]);
            out[1] = make_float4(acc[i][4], acc[i][5], acc[i][6], acc[i][7]);
        }
    }
}

// ---------------------------------------------------------------------------
// Init aggregation buffer with self-loop contribution + bias:
//   agg[i,:] = h[i,:] * dinv[i]^2 + b[:]
// ---------------------------------------------------------------------------
__global__ void init_agg_kernel(const float* __restrict__ h,
                                const float* __restrict__ b,
                                float* __restrict__ agg, int n) {
    int t = blockIdx.x * blockDim.x + threadIdx.x;
    if (t >= n * 32) return;
    int node = t >> 5;
    int c4 = t & 31;
    float di = g_dinv[node];
    float sl = di * di;
    float4 hv = ((const float4*)h)[(size_t)node * 32 + c4];
    float4 bv = ((const float4*)b)[c4];
    float4 o;
    o.x = fmaf(hv.x, sl, bv.x);
    o.y = fmaf(hv.y, sl, bv.y);
    o.z = fmaf(hv.z, sl, bv.z);
    o.w = fmaf(hv.w, sl, bv.w);
    ((float4*)agg)[(size_t)node * 32 + c4] = o;
}

// ---------------------------------------------------------------------------
// Edge scatter: one warp per edge.
//   agg[dst,:] += h[src,:] * coef[e]
// ---------------------------------------------------------------------------
__global__ void __launch_bounds__(256)
scatter_kernel(const float* __restrict__ h, float* __restrict__ agg, int E) {
    int warp = (blockIdx.x * blockDim.x + threadIdx.x) >> 5;
    int lane = threadIdx.x & 31;
    if (warp >= E) return;
    int s = g_idx[warp];
    int d = g_idx[E + warp];
    float coef = g_coef[warp];
    float4 v = ((const float4*)(h + (size_t)s * CH))[lane];
    float* p = agg + (size_t)d * CH + lane * 4;
    asm volatile(
        "red.global.add.v4.f32 [%0], {%1, %2, %3, %4};"
        :: "l"(p), "f"(v.x * coef), "f"(v.y * coef), "f"(v.z * coef), "f"(v.w * coef)
        : "memory");
}

// ---------------------------------------------------------------------------
// Launch
// ---------------------------------------------------------------------------
extern "C" void kernel_launch(void* const* d_in, const int* in_sizes, int n_in,
                              void* d_out, int out_size) {
    const float* x  = (const float*)d_in[0];       // [N,128]
    const void*  ei = d_in[1];                     // [2,E] int64 OR int32
    const float* W1 = (const float*)d_in[2];       // [128,128]
    const float* b1 = (const float*)d_in[3];       // [128]
    const float* W2 = (const float*)d_in[4];       // [128,128]
    const float* b2 = (const float*)d_in[5];       // [128]
    float*       out = (float*)d_out;              // [N,128]

    const int N = in_sizes[0] / CH;
    const int E = in_sizes[1] / 2;

    float *hp = nullptr, *aggp = nullptr;
    cudaGetSymbolAddress((void**)&hp, g_h);
    cudaGetSymbolAddress((void**)&aggp, g_agg);

    const int T = 256;
    const int gemm_grid = (N + 127) / 128;
    const int edge_grid = (E + T - 1) / T;
    const int warp_grid = (E * 32 + T - 1) / T;
    const int node_grid = (N + T - 1) / T;
    const int nv4_grid = (N * 32 + T - 1) / T;
    const int conv_grid = (2 * E + T - 1) / T;

    // ---- Index conversion (dtype-robust) + degrees + dinv + coef ----
    detect_zero_kernel<<<1, 32>>>();
    detect_kernel<<<1, 256>>>((const unsigned int*)ei, 2 * E);  // words if int32; conservative
    convert_kernel<<<conv_grid, T>>>(ei, 2 * E);
    zero_deg_kernel<<<node_grid, T>>>(N);
    deg_kernel<<<edge_grid, T>>>(E);
    dinv_kernel<<<node_grid, T>>>(N);
    coef_kernel<<<edge_grid, T>>>(E);

    // ---- Layer 1 ----
    gemm128_kernel<false><<<gemm_grid, T>>>(x, W1, hp, N);
    init_agg_kernel<<<nv4_grid, T>>>(hp, b1, aggp, N);
    scatter_kernel<<<warp_grid, T>>>(hp, aggp, E);

    // ---- Layer 2 (relu fused into GEMM A-load; aggregates into d_out) ----
    gemm128_kernel<true><<<gemm_grid, T>>>(aggp, W2, hp, N);
    init_agg_kernel<<<nv4_grid, T>>>(hp, b2, out, N);
    scatter_kernel<<<warp_grid, T>>>(hp, out, E);
}

// round 3
// speedup vs baseline: 1.5399x; 1.5399x over previous
#include <cuda_runtime.h>
#include <cstdint>

// ---------------------------------------------------------------------------
// GCNEncoder: 2-layer GCN
//   h1 = relu( Dinv (A+I) Dinv (x @ W1) + b1 )
//   out =      Dinv (A+I) Dinv (h1 @ W2) + b2
// N = 100000 nodes, E = 1600000 edges, 128 channels.
// R3: pull-based aggregation. Build CSR (by dst) once per launch, then each
// node's warp gathers h[src]*coef into registers — zero float atomics.
// ---------------------------------------------------------------------------

#define MAX_N 100000
#define MAX_E 1600000
#define CH 128

__device__ alignas(16) float g_h[(size_t)MAX_N * CH];    // GEMM output
__device__ alignas(16) float g_agg[(size_t)MAX_N * CH];  // layer-1 agg buffer
__device__ float g_dinv[MAX_N];
__device__ int   g_deg[MAX_N];
__device__ int   g_row[MAX_N];         // CSR row start (by dst)
__device__ int   g_cur[MAX_N];         // fill cursor
__device__ int   g_idx[2 * MAX_E];     // converted int32 src/dst
__device__ int2  g_csr[MAX_E];         // (src, coef-as-int) per edge, grouped by dst
__device__ unsigned int g_or_hi;       // dtype-detection accumulator
__device__ unsigned int g_alloc;       // CSR region allocator

// ---------------------------------------------------------------------------
// Init: zero degrees + detection/allocator state
// ---------------------------------------------------------------------------
__global__ void init_kernel(int n) {
    int i = blockIdx.x * blockDim.x + threadIdx.x;
    if (i < n) g_deg[i] = 0;
    if (i == 0) { g_or_hi = 0u; g_alloc = 0u; }
}

// ---------------------------------------------------------------------------
// Edge-index dtype detection: int64 values in [0,N) have zero high words;
// int32 random values essentially never have all odd words zero.
// ---------------------------------------------------------------------------
__global__ void detect_kernel(const unsigned int* __restrict__ w, int nwords) {
    unsigned int v = 0;
    for (int i = threadIdx.x; i < 1024; i += blockDim.x) {
        int idx = 2 * i + 1;
        if (idx < nwords) v |= w[idx];
    }
    for (int off = 16; off > 0; off >>= 1)
        v |= __shfl_down_sync(0xFFFFFFFFu, v, off);
    if ((threadIdx.x & 31) == 0 && v) atomicOr(&g_or_hi, v);
}

// Convert indices to int32 and count in-degrees (dst half) in one pass.
__global__ void convert_kernel(const void* __restrict__ ei, int E) {
    int i = blockIdx.x * blockDim.x + threadIdx.x;
    if (i >= 2 * E) return;
    int v;
    if (g_or_hi == 0u) v = (int)((const long long*)ei)[i];
    else               v = ((const int*)ei)[i];
    g_idx[i] = v;
    if (i >= E) atomicAdd(&g_deg[v], 1);
}

__global__ void dinv_kernel(int n) {
    int i = blockIdx.x * blockDim.x + threadIdx.x;
    if (i < n) g_dinv[i] = rsqrtf((float)g_deg[i] + 1.0f);
}

// ---------------------------------------------------------------------------
// Allocate contiguous CSR ranges per node: block-local exclusive scan of
// degrees + one atomicAdd per block for the base. Row ordering across blocks
// is run-dependent but the CSR is always valid.
// ---------------------------------------------------------------------------
__global__ void __launch_bounds__(256)
alloc_rows_kernel(int n) {
    int i = blockIdx.x * 256 + threadIdx.x;
    int lane = threadIdx.x & 31;
    int wid = threadIdx.x >> 5;
    int d = (i < n) ? g_deg[i] : 0;

    // warp inclusive scan
    int v = d;
#pragma unroll
    for (int off = 1; off < 32; off <<= 1) {
        int t = __shfl_up_sync(0xFFFFFFFFu, v, off);
        if (lane >= off) v += t;
    }
    __shared__ int wsum[8];
    __shared__ int woff[8];
    __shared__ int base;
    if (lane == 31) wsum[wid] = v;
    __syncthreads();
    if (threadIdx.x == 0) {
        int run = 0;
#pragma unroll
        for (int w = 0; w < 8; w++) { woff[w] = run; run += wsum[w]; }
        base = (int)atomicAdd(&g_alloc, (unsigned int)run);
    }
    __syncthreads();
    if (i < n) {
        int start = base + woff[wid] + (v - d);  // exclusive position
        g_row[i] = start;
        g_cur[i] = start;
    }
}

// Fill CSR: for each edge, grab a slot in dst's range, store (src, coef).
__global__ void csr_fill_kernel(int E) {
    int e = blockIdx.x * blockDim.x + threadIdx.x;
    if (e >= E) return;
    int s = g_idx[e];
    int d = g_idx[E + e];
    float coef = g_dinv[s] * g_dinv[d];
    int pos = atomicAdd(&g_cur[d], 1);
    g_csr[pos] = make_int2(s, __float_as_int(coef));
}

// ---------------------------------------------------------------------------
// GEMM: C[n,128] = act(A[n,128]) @ W[128,128]
// 128x128 tile, 256 threads, 8x8 register blocking, BK=16.
// ---------------------------------------------------------------------------
template <bool RELU>
__global__ void __launch_bounds__(256)
gemm128_kernel(const float* __restrict__ A, const float* __restrict__ W,
               float* __restrict__ C, int n) {
    __shared__ float As[16][CH + 4];
    __shared__ float Ws[16][CH];

    const int block_row = blockIdx.x * 128;
    const int tid = threadIdx.x;
    const int tx = tid & 15;
    const int ty = tid >> 4;

    float acc[8][8];
#pragma unroll
    for (int i = 0; i < 8; i++)
#pragma unroll
        for (int j = 0; j < 8; j++) acc[i][j] = 0.0f;

    for (int k0 = 0; k0 < CH; k0 += 16) {
#pragma unroll
        for (int i = 0; i < 8; i++) {
            int idx = tid + i * 256;
            int r = idx >> 4;
            int c = idx & 15;
            int gr = block_row + r;
            float v = 0.0f;
            if (gr < n) {
                v = A[(size_t)gr * CH + k0 + c];
                if (RELU) v = fmaxf(v, 0.0f);
            }
            As[c][r] = v;
        }
#pragma unroll
        for (int i = 0; i < 8; i++) {
            int idx = tid + i * 256;
            int r = idx >> 7;
            int c = idx & 127;
            Ws[r][c] = W[(k0 + r) * CH + c];
        }
        __syncthreads();

#pragma unroll
        for (int k = 0; k < 16; k++) {
            float a[8], b[8];
#pragma unroll
            for (int i = 0; i < 8; i++) a[i] = As[k][ty * 8 + i];
#pragma unroll
            for (int j = 0; j < 8; j++) b[j] = Ws[k][tx * 8 + j];
#pragma unroll
            for (int i = 0; i < 8; i++)
#pragma unroll
                for (int j = 0; j < 8; j++) acc[i][j] = fmaf(a[i], b[j], acc[i][j]);
        }
        __syncthreads();
    }

#pragma unroll
    for (int i = 0; i < 8; i++) {
        int gr = block_row + ty * 8 + i;
        if (gr < n) {
            float4* out = (float4*)(C + (size_t)gr * CH + tx * 8);
            out[0] = make_float4(acc[i][0], acc[i][1], acc[i][2], acc[i][3]);
            out[1] = make_float4(acc[i][4], acc[i][5], acc[i][6], acc[i][7]);
        }
    }
}

// ---------------------------------------------------------------------------
// Pull aggregation: one warp per node.
//   out[i,:] = sum_{e: dst=i} h[src_e,:]*coef_e  +  h[i,:]*dinv[i]^2 + b[:]
// Register accumulation, no atomics. Each lane owns one float4 (4 channels).
// ---------------------------------------------------------------------------
__global__ void __launch_bounds__(256)
gather_kernel(const float* __restrict__ h, const float* __restrict__ b,
              float* __restrict__ out, int n) {
    int node = (blockIdx.x * blockDim.x + threadIdx.x) >> 5;
    int lane = threadIdx.x & 31;
    if (node >= n) return;

    int start = g_row[node];
    int deg = g_deg[node];
    float di = g_dinv[node];
    float sl = di * di;

    float4 hv = ((const float4*)(h + (size_t)node * CH))[lane];
    float4 bv = ((const float4*)b)[lane];
    float4 acc;
    acc.x = fmaf(hv.x, sl, bv.x);
    acc.y = fmaf(hv.y, sl, bv.y);
    acc.z = fmaf(hv.z, sl, bv.z);
    acc.w = fmaf(hv.w, sl, bv.w);

    for (int j0 = 0; j0 < deg; j0 += 32) {
        int nn = min(32, deg - j0);
        int2 e = make_int2(0, 0);
        if (lane < nn) e = g_csr[start + j0 + lane];
#pragma unroll 4
        for (int k = 0; k < nn; k++) {
            int s = __shfl_sync(0xFFFFFFFFu, e.x, k);
            float c = __int_as_float(__shfl_sync(0xFFFFFFFFu, e.y, k));
            float4 v = ((const float4*)(h + (size_t)s * CH))[lane];
            acc.x = fmaf(v.x, c, acc.x);
            acc.y = fmaf(v.y, c, acc.y);
            acc.z = fmaf(v.z, c, acc.z);
            acc.w = fmaf(v.w, c, acc.w);
        }
    }
    ((float4*)(out + (size_t)node * CH))[lane] = acc;
}

// ---------------------------------------------------------------------------
// Launch
// ---------------------------------------------------------------------------
extern "C" void kernel_launch(void* const* d_in, const int* in_sizes, int n_in,
                              void* d_out, int out_size) {
    const float* x  = (const float*)d_in[0];       // [N,128]
    const void*  ei = d_in[1];                     // [2,E] int64 OR int32
    const float* W1 = (const float*)d_in[2];       // [128,128]
    const float* b1 = (const float*)d_in[3];       // [128]
    const float* W2 = (const float*)d_in[4];       // [128,128]
    const float* b2 = (const float*)d_in[5];       // [128]
    float*       out = (float*)d_out;              // [N,128]

    const int N = in_sizes[0] / CH;
    const int E = in_sizes[1] / 2;

    float *hp = nullptr, *aggp = nullptr;
    cudaGetSymbolAddress((void**)&hp, g_h);
    cudaGetSymbolAddress((void**)&aggp, g_agg);

    const int T = 256;
    const int gemm_grid = (N + 127) / 128;
    const int edge_grid = (E + T - 1) / T;
    const int node_grid = (N + T - 1) / T;
    const int conv_grid = (2 * E + T - 1) / T;
    const int warp_grid = (N * 32 + T - 1) / T;    // one warp per node

    // ---- Preprocessing: indices, degrees, dinv, CSR ----
    init_kernel<<<node_grid, T>>>(N);
    detect_kernel<<<1, 256>>>((const unsigned int*)ei, 2 * E);
    convert_kernel<<<conv_grid, T>>>(ei, E);
    dinv_kernel<<<node_grid, T>>>(N);
    alloc_rows_kernel<<<node_grid, T>>>(N);
    csr_fill_kernel<<<edge_grid, T>>>(E);

    // ---- Layer 1 ----
    gemm128_kernel<false><<<gemm_grid, T>>>(x, W1, hp, N);
    gather_kernel<<<warp_grid, T>>>(hp, b1, aggp, N);

    // ---- Layer 2 (relu fused into GEMM A-load; gathers into d_out) ----
    gemm128_kernel<true><<<gemm_grid, T>>>(aggp, W2, hp, N);
    gather_kernel<<<warp_grid, T>>>(hp, b2, out, N);
}

// round 5
// speedup vs baseline: 2.0106x; 1.3057x over previous
#include <cuda_runtime.h>
#include <cstdint>

// ---------------------------------------------------------------------------
// GCNEncoder: 2-layer GCN (pull-based CSR gather + 3xTF32 tensor-core GEMM)
//   h1 = relu( Dinv (A+I) Dinv (x @ W1) + b1 )
//   out =      Dinv (A+I) Dinv (h1 @ W2) + b2
// N = 100000, E = 1600000, CH = 128.
// ---------------------------------------------------------------------------

#define MAX_N 100000
#define MAX_E 1600000
#define CH 128

__device__ alignas(16) float g_h[(size_t)MAX_N * CH];
__device__ alignas(16) float g_agg[(size_t)MAX_N * CH];
__device__ float g_dinv[MAX_N];
__device__ int   g_deg[MAX_N];
__device__ int   g_row[MAX_N];
__device__ int   g_cur[MAX_N];
__device__ int   g_idx[2 * MAX_E];
__device__ int2  g_csr[MAX_E];
__device__ unsigned int g_or_hi;
__device__ unsigned int g_alloc;

// ---------------------------------------------------------------------------
// (1) init + dtype detection. int64 indices in [0,N) have zero high words.
// ---------------------------------------------------------------------------
__global__ void init_detect_kernel(const unsigned int* __restrict__ w,
                                   int nwords, int n) {
    int i = blockIdx.x * blockDim.x + threadIdx.x;
    if (i < n) g_deg[i] = 0;
    if (i == 0) { g_alloc = 0u; }
    if (blockIdx.x == 0) {
        unsigned int v = 0;
        for (int j = threadIdx.x; j < 1024; j += blockDim.x) {
            int idx = 2 * j + 1;
            if (idx < nwords) v |= w[idx];
        }
        for (int off = 16; off > 0; off >>= 1)
            v |= __shfl_down_sync(0xFFFFFFFFu, v, off);
        __shared__ unsigned int sv[8];
        if ((threadIdx.x & 31) == 0) sv[threadIdx.x >> 5] = v;
        __syncthreads();
        if (threadIdx.x == 0) {
            unsigned int r = 0;
            for (int wz = 0; wz < (int)(blockDim.x >> 5); wz++) r |= sv[wz];
            g_or_hi = r;
        }
    }
}

// (2) convert indices to int32 + count in-degrees (dst half).
__global__ void convert_kernel(const void* __restrict__ ei, int E) {
    int i = blockIdx.x * blockDim.x + threadIdx.x;
    if (i >= 2 * E) return;
    int v;
    if (g_or_hi == 0u) v = (int)((const long long*)ei)[i];
    else               v = ((const int*)ei)[i];
    g_idx[i] = v;
    if (i >= E) atomicAdd(&g_deg[v], 1);
}

// ---------------------------------------------------------------------------
// (3) dinv + CSR row allocation (block scan + atomic base).
// ---------------------------------------------------------------------------
__global__ void __launch_bounds__(256)
dinv_alloc_kernel(int n) {
    int i = blockIdx.x * 256 + threadIdx.x;
    int lane = threadIdx.x & 31;
    int wid = threadIdx.x >> 5;
    int d = (i < n) ? g_deg[i] : 0;
    if (i < n) g_dinv[i] = rsqrtf((float)d + 1.0f);

    int v = d;
#pragma unroll
    for (int off = 1; off < 32; off <<= 1) {
        int t = __shfl_up_sync(0xFFFFFFFFu, v, off);
        if (lane >= off) v += t;
    }
    __shared__ int wsum[8];
    __shared__ int woff[8];
    __shared__ int base;
    if (lane == 31) wsum[wid] = v;
    __syncthreads();
    if (threadIdx.x == 0) {
        int run = 0;
#pragma unroll
        for (int w = 0; w < 8; w++) { woff[w] = run; run += wsum[w]; }
        base = (int)atomicAdd(&g_alloc, (unsigned int)run);
    }
    __syncthreads();
    if (i < n) {
        int start = base + woff[wid] + (v - d);
        g_row[i] = start;
        g_cur[i] = start;
    }
}

// (5) Fill CSR: (src, coef) per edge, grouped by dst.
__global__ void csr_fill_kernel(int E) {
    int e = blockIdx.x * blockDim.x + threadIdx.x;
    if (e >= E) return;
    int s = g_idx[e];
    int d = g_idx[E + e];
    float coef = g_dinv[s] * g_dinv[d];
    int pos = atomicAdd(&g_cur[d], 1);
    g_csr[pos] = make_int2(s, __float_as_int(coef));
}

// ---------------------------------------------------------------------------
// (4,7) GEMM via 3xTF32 mma.sync: C[n,128] = act(A[n,128]) @ W[128,128]
// Block 128x128, 256 threads (8 warps as 4x2 -> 32x64 per warp), BK=16.
// Each operand split x = hi + lo (hi = round-to-tf32); accumulate
// hi*hi + hi*lo + lo*hi in fp32 -> ~2e-7 rel error.
// ---------------------------------------------------------------------------
__device__ __forceinline__ float tf32_rna(float x) {
    unsigned r;                               // tf32 cvt needs .b32 dest
    asm("cvt.rna.tf32.f32 %0, %1;" : "=r"(r) : "f"(x));
    return __uint_as_float(r);                // tf32 bits are valid fp32
}

__device__ __forceinline__ void mma_tf32(float* c, const unsigned* a, const unsigned* b) {
    asm volatile(
        "mma.sync.aligned.m16n8k8.row.col.f32.tf32.tf32.f32 "
        "{%0,%1,%2,%3}, {%4,%5,%6,%7}, {%8,%9}, {%0,%1,%2,%3};"
        : "+f"(c[0]), "+f"(c[1]), "+f"(c[2]), "+f"(c[3])
        : "r"(a[0]), "r"(a[1]), "r"(a[2]), "r"(a[3]), "r"(b[0]), "r"(b[1]));
}

#define APAD 20    // A smem row stride (16 + 4) -> conflict-free frag loads
#define WPAD 136   // W smem row stride (128 + 8)

template <bool RELU>
__global__ void __launch_bounds__(256)
gemm_tf32_kernel(const float* __restrict__ A, const float* __restrict__ W,
                 float* __restrict__ C, int n) {
    __shared__ float As[2][128][APAD];   // [hi/lo][m][k]
    __shared__ float Ws[2][16][WPAD];    // [hi/lo][k][n]

    const int block_row = blockIdx.x * 128;
    const int tid = threadIdx.x;
    const int lane = tid & 31;
    const int wid = tid >> 5;
    const int wm = (wid & 3) * 32;       // warp row base
    const int wn = (wid >> 2) * 64;      // warp col base
    const int gid = lane >> 2;           // 0..7
    const int tig = lane & 3;            // 0..3

    float acc[2][8][4];
#pragma unroll
    for (int mt = 0; mt < 2; mt++)
#pragma unroll
        for (int nt = 0; nt < 8; nt++)
#pragma unroll
            for (int r = 0; r < 4; r++) acc[mt][nt][r] = 0.0f;

    for (int k0 = 0; k0 < CH; k0 += 16) {
        // Load A tile 128x16: thread -> row = tid>>1, k-quad = (tid&1)*8
        {
            int r = tid >> 1;
            int kb = (tid & 1) * 8;
            int gr = block_row + r;
            float4 v0 = make_float4(0.f, 0.f, 0.f, 0.f), v1 = v0;
            if (gr < n) {
                const float4* src = (const float4*)(A + (size_t)gr * CH + k0 + kb);
                v0 = src[0];
                v1 = src[1];
                if (RELU) {
                    v0.x = fmaxf(v0.x, 0.f); v0.y = fmaxf(v0.y, 0.f);
                    v0.z = fmaxf(v0.z, 0.f); v0.w = fmaxf(v0.w, 0.f);
                    v1.x = fmaxf(v1.x, 0.f); v1.y = fmaxf(v1.y, 0.f);
                    v1.z = fmaxf(v1.z, 0.f); v1.w = fmaxf(v1.w, 0.f);
                }
            }
            float4 h0 = make_float4(tf32_rna(v0.x), tf32_rna(v0.y), tf32_rna(v0.z), tf32_rna(v0.w));
            float4 h1 = make_float4(tf32_rna(v1.x), tf32_rna(v1.y), tf32_rna(v1.z), tf32_rna(v1.w));
            float4 l0 = make_float4(v0.x - h0.x, v0.y - h0.y, v0.z - h0.z, v0.w - h0.w);
            float4 l1 = make_float4(v1.x - h1.x, v1.y - h1.y, v1.z - h1.z, v1.w - h1.w);
            *(float4*)&As[0][r][kb]     = h0;
            *(float4*)&As[0][r][kb + 4] = h1;
            *(float4*)&As[1][r][kb]     = l0;
            *(float4*)&As[1][r][kb + 4] = l1;
        }
        // Load W tile 16x128: thread -> k = tid>>4, n-oct = (tid&15)*8
        {
            int kr = tid >> 4;
            int nb = (tid & 15) * 8;
            const float4* src = (const float4*)(W + (size_t)(k0 + kr) * CH + nb);
            float4 v0 = src[0];
            float4 v1 = src[1];
            float4 h0 = make_float4(tf32_rna(v0.x), tf32_rna(v0.y), tf32_rna(v0.z), tf32_rna(v0.w));
            float4 h1 = make_float4(tf32_rna(v1.x), tf32_rna(v1.y), tf32_rna(v1.z), tf32_rna(v1.w));
            float4 l0 = make_float4(v0.x - h0.x, v0.y - h0.y, v0.z - h0.z, v0.w - h0.w);
            float4 l1 = make_float4(v1.x - h1.x, v1.y - h1.y, v1.z - h1.z, v1.w - h1.w);
            *(float4*)&Ws[0][kr][nb]     = h0;
            *(float4*)&Ws[0][kr][nb + 4] = h1;
            *(float4*)&Ws[1][kr][nb]     = l0;
            *(float4*)&Ws[1][kr][nb + 4] = l1;
        }
        __syncthreads();

#pragma unroll
        for (int ks = 0; ks < 2; ks++) {
            int kk = ks * 8;
            unsigned ah[2][4], al[2][4];
#pragma unroll
            for (int mt = 0; mt < 2; mt++) {
                int m = wm + mt * 16;
                ah[mt][0] = __float_as_uint(As[0][m + gid][kk + tig]);
                ah[mt][1] = __float_as_uint(As[0][m + gid + 8][kk + tig]);
                ah[mt][2] = __float_as_uint(As[0][m + gid][kk + tig + 4]);
                ah[mt][3] = __float_as_uint(As[0][m + gid + 8][kk + tig + 4]);
                al[mt][0] = __float_as_uint(As[1][m + gid][kk + tig]);
                al[mt][1] = __float_as_uint(As[1][m + gid + 8][kk + tig]);
                al[mt][2] = __float_as_uint(As[1][m + gid][kk + tig + 4]);
                al[mt][3] = __float_as_uint(As[1][m + gid + 8][kk + tig + 4]);
            }
            unsigned bh[8][2], bl[8][2];
#pragma unroll
            for (int nt = 0; nt < 8; nt++) {
                int nn = wn + nt * 8 + gid;
                bh[nt][0] = __float_as_uint(Ws[0][kk + tig][nn]);
                bh[nt][1] = __float_as_uint(Ws[0][kk + tig + 4][nn]);
                bl[nt][0] = __float_as_uint(Ws[1][kk + tig][nn]);
                bl[nt][1] = __float_as_uint(Ws[1][kk + tig + 4][nn]);
            }
#pragma unroll
            for (int mt = 0; mt < 2; mt++)
#pragma unroll
                for (int nt = 0; nt < 8; nt++) {
                    mma_tf32(acc[mt][nt], ah[mt], bh[nt]);  // hi*hi
                    mma_tf32(acc[mt][nt], ah[mt], bl[nt]);  // hi*lo
                    mma_tf32(acc[mt][nt], al[mt], bh[nt]);  // lo*hi
                }
        }
        __syncthreads();
    }

    // Epilogue: c0,c1 at (row, 2*tig), (row, 2*tig+1); c2,c3 at row+8.
#pragma unroll
    for (int mt = 0; mt < 2; mt++) {
#pragma unroll
        for (int nt = 0; nt < 8; nt++) {
            int r0 = block_row + wm + mt * 16 + gid;
            int cb = wn + nt * 8 + 2 * tig;
            if (r0 < n)
                *(float2*)(C + (size_t)r0 * CH + cb) = make_float2(acc[mt][nt][0], acc[mt][nt][1]);
            if (r0 + 8 < n)
                *(float2*)(C + (size_t)(r0 + 8) * CH + cb) = make_float2(acc[mt][nt][2], acc[mt][nt][3]);
        }
    }
}

// ---------------------------------------------------------------------------
// (6,8) Pull aggregation: one warp per node, register accumulation.
//   out[i,:] = sum_{e:dst=i} h[src_e,:]*coef_e + h[i,:]*dinv^2 + b[:]
// ---------------------------------------------------------------------------
__global__ void __launch_bounds__(256)
gather_kernel(const float* __restrict__ h, const float* __restrict__ b,
              float* __restrict__ out, int n) {
    int node = (blockIdx.x * blockDim.x + threadIdx.x) >> 5;
    int lane = threadIdx.x & 31;
    if (node >= n) return;

    int start = g_row[node];
    int deg = g_deg[node];
    float di = g_dinv[node];
    float sl = di * di;

    float4 hv = ((const float4*)(h + (size_t)node * CH))[lane];
    float4 bv = ((const float4*)b)[lane];
    float4 acc;
    acc.x = fmaf(hv.x, sl, bv.x);
    acc.y = fmaf(hv.y, sl, bv.y);
    acc.z = fmaf(hv.z, sl, bv.z);
    acc.w = fmaf(hv.w, sl, bv.w);

    for (int j0 = 0; j0 < deg; j0 += 32) {
        int nn = min(32, deg - j0);
        int2 e = make_int2(0, 0);
        if (lane < nn) e = g_csr[start + j0 + lane];
#pragma unroll 4
        for (int k = 0; k < nn; k++) {
            int s = __shfl_sync(0xFFFFFFFFu, e.x, k);
            float c = __int_as_float(__shfl_sync(0xFFFFFFFFu, e.y, k));
            float4 v = ((const float4*)(h + (size_t)s * CH))[lane];
            acc.x = fmaf(v.x, c, acc.x);
            acc.y = fmaf(v.y, c, acc.y);
            acc.z = fmaf(v.z, c, acc.z);
            acc.w = fmaf(v.w, c, acc.w);
        }
    }
    ((float4*)(out + (size_t)node * CH))[lane] = acc;
}

// ---------------------------------------------------------------------------
// Launch. Order puts gemm layer-1 at position 4 (the ncu-profiled slot).
// ---------------------------------------------------------------------------
extern "C" void kernel_launch(void* const* d_in, const int* in_sizes, int n_in,
                              void* d_out, int out_size) {
    const float* x  = (const float*)d_in[0];
    const void*  ei = d_in[1];
    const float* W1 = (const float*)d_in[2];
    const float* b1 = (const float*)d_in[3];
    const float* W2 = (const float*)d_in[4];
    const float* b2 = (const float*)d_in[5];
    float*       out = (float*)d_out;

    const int N = in_sizes[0] / CH;
    const int E = in_sizes[1] / 2;

    float *hp = nullptr, *aggp = nullptr;
    cudaGetSymbolAddress((void**)&hp, g_h);
    cudaGetSymbolAddress((void**)&aggp, g_agg);

    const int T = 256;
    const int gemm_grid = (N + 127) / 128;
    const int edge_grid = (E + T - 1) / T;
    const int node_grid = (N + T - 1) / T;
    const int conv_grid = (2 * E + T - 1) / T;
    const int warp_grid = (N * 32 + T - 1) / T;

    init_detect_kernel<<<node_grid, T>>>((const unsigned int*)ei, 2 * E, N);   // 1
    convert_kernel<<<conv_grid, T>>>(ei, E);                                   // 2
    dinv_alloc_kernel<<<node_grid, T>>>(N);                                    // 3
    gemm_tf32_kernel<false><<<gemm_grid, T>>>(x, W1, hp, N);                   // 4 (profiled)
    csr_fill_kernel<<<edge_grid, T>>>(E);                                      // 5
    gather_kernel<<<warp_grid, T>>>(hp, b1, aggp, N);                          // 6
    gemm_tf32_kernel<true><<<gemm_grid, T>>>(aggp, W2, hp, N);                 // 7
    gather_kernel<<<warp_grid, T>>>(hp, b2, out, N);                           // 8
}

// round 8
// speedup vs baseline: 2.2408x; 1.1144x over previous
#include <cuda_runtime.h>
#include <cstdint>

// ---------------------------------------------------------------------------
// GCNEncoder: 2-layer GCN (CSR gather + 3xTF32 tensor-core GEMM, cp.async)
//   h1 = relu( Dinv (A+I) Dinv (x @ W1) + b1 )
//   out =      Dinv (A+I) Dinv (h1 @ W2) + b2
// N = 100000, E = 1600000, CH = 128.
// ---------------------------------------------------------------------------

#define MAX_N 100000
#define MAX_E 1600000
#define CH 128

__device__ alignas(16) float g_h[(size_t)MAX_N * CH];
__device__ alignas(16) float g_agg[(size_t)MAX_N * CH];
__device__ float g_dinv[MAX_N];
__device__ int   g_deg[MAX_N];
__device__ int   g_row[MAX_N];
__device__ int   g_cur[MAX_N];
__device__ int   g_idx[2 * MAX_E];
__device__ int2  g_csr[MAX_E];
__device__ unsigned int g_or_hi;
__device__ unsigned int g_alloc;

// ---------------------------------------------------------------------------
// (1) init + dtype detection. int64 indices in [0,N) have zero high words.
// ---------------------------------------------------------------------------
__global__ void init_detect_kernel(const unsigned int* __restrict__ w,
                                   int nwords, int n) {
    int i = blockIdx.x * blockDim.x + threadIdx.x;
    if (i < n) g_deg[i] = 0;
    if (i == 0) { g_alloc = 0u; }
    if (blockIdx.x == 0) {
        unsigned int v = 0;
        for (int j = threadIdx.x; j < 1024; j += blockDim.x) {
            int idx = 2 * j + 1;
            if (idx < nwords) v |= w[idx];
        }
        for (int off = 16; off > 0; off >>= 1)
            v |= __shfl_down_sync(0xFFFFFFFFu, v, off);
        __shared__ unsigned int sv[8];
        if ((threadIdx.x & 31) == 0) sv[threadIdx.x >> 5] = v;
        __syncthreads();
        if (threadIdx.x == 0) {
            unsigned int r = 0;
            for (int wz = 0; wz < (int)(blockDim.x >> 5); wz++) r |= sv[wz];
            g_or_hi = r;
        }
    }
}

// (2) convert indices to int32 + count in-degrees (dst half).
__global__ void convert_kernel(const void* __restrict__ ei, int E) {
    int i = blockIdx.x * blockDim.x + threadIdx.x;
    if (i >= 2 * E) return;
    int v;
    if (g_or_hi == 0u) v = (int)((const long long*)ei)[i];
    else               v = ((const int*)ei)[i];
    g_idx[i] = v;
    if (i >= E) atomicAdd(&g_deg[v], 1);
}

// ---------------------------------------------------------------------------
// (3) dinv + CSR row allocation (block scan + atomic base).
// ---------------------------------------------------------------------------
__global__ void __launch_bounds__(256)
dinv_alloc_kernel(int n) {
    int i = blockIdx.x * 256 + threadIdx.x;
    int lane = threadIdx.x & 31;
    int wid = threadIdx.x >> 5;
    int d = (i < n) ? g_deg[i] : 0;
    if (i < n) g_dinv[i] = rsqrtf((float)d + 1.0f);

    int v = d;
#pragma unroll
    for (int off = 1; off < 32; off <<= 1) {
        int t = __shfl_up_sync(0xFFFFFFFFu, v, off);
        if (lane >= off) v += t;
    }
    __shared__ int wsum[8];
    __shared__ int woff[8];
    __shared__ int base;
    if (lane == 31) wsum[wid] = v;
    __syncthreads();
    if (threadIdx.x == 0) {
        int run = 0;
#pragma unroll
        for (int w = 0; w < 8; w++) { woff[w] = run; run += wsum[w]; }
        base = (int)atomicAdd(&g_alloc, (unsigned int)run);
    }
    __syncthreads();
    if (i < n) {
        int start = base + woff[wid] + (v - d);
        g_row[i] = start;
        g_cur[i] = start;
    }
}

// (5) Fill CSR: (src, coef) per edge, grouped by dst.
__global__ void csr_fill_kernel(int E) {
    int e = blockIdx.x * blockDim.x + threadIdx.x;
    if (e >= E) return;
    int s = g_idx[e];
    int d = g_idx[E + e];
    float coef = g_dinv[s] * g_dinv[d];
    int pos = atomicAdd(&g_cur[d], 1);
    g_csr[pos] = make_int2(s, __float_as_int(coef));
}

// ---------------------------------------------------------------------------
// (4,7) GEMM via 3xTF32 mma.sync, cp.async double-buffered.
// C[n,128] = act(A[n,128]) @ W[128,128]
// Block 128x128, 256 threads (8 warps as 4x2 -> 32x64/warp), BK=16, 2 stages.
// Raw fp32 tiles in smem; hi/lo split at fragment-load time.
// OOB tail rows: source address CLAMPED in-bounds, src-size=0 zero-fills.
// ---------------------------------------------------------------------------
__device__ __forceinline__ float tf32_rna(float x) {
    unsigned r;
    asm("cvt.rna.tf32.f32 %0, %1;" : "=r"(r) : "f"(x));
    return __uint_as_float(r);
}

__device__ __forceinline__ void mma_tf32(float* c, const unsigned* a, const unsigned* b) {
    asm volatile(
        "mma.sync.aligned.m16n8k8.row.col.f32.tf32.tf32.f32 "
        "{%0,%1,%2,%3}, {%4,%5,%6,%7}, {%8,%9}, {%0,%1,%2,%3};"
        : "+f"(c[0]), "+f"(c[1]), "+f"(c[2]), "+f"(c[3])
        : "r"(a[0]), "r"(a[1]), "r"(a[2]), "r"(a[3]), "r"(b[0]), "r"(b[1]));
}

__device__ __forceinline__ void cpa16(unsigned dst, const void* src, bool pred) {
    int sz = pred ? 16 : 0;
    asm volatile("cp.async.cg.shared.global [%0], [%1], 16, %2;"
                 :: "r"(dst), "l"(src), "r"(sz) : "memory");
}
#define CP_COMMIT() asm volatile("cp.async.commit_group;" ::: "memory")
#define CP_WAIT0()  asm volatile("cp.async.wait_group 0;" ::: "memory")

#define APAD 20    // A row stride (floats): conflict-free frags, 16B-aligned
#define WPAD 136   // W row stride (floats): conflict-free frags, 16B-aligned

template <bool RELU>
__global__ void __launch_bounds__(256, 2)
gemm_tf32_kernel(const float* __restrict__ A, const float* __restrict__ W,
                 float* __restrict__ C, int n) {
    __shared__ alignas(16) float As[2][128][APAD];
    __shared__ alignas(16) float Ws[2][16][WPAD];

    const int block_row = blockIdx.x * 128;
    const int tid = threadIdx.x;
    const int lane = tid & 31;
    const int wid = tid >> 5;
    const int wm = (wid & 3) * 32;
    const int wn = (wid >> 2) * 64;
    const int gid = lane >> 2;
    const int tig = lane & 3;

    // cp.async chunk mapping (2 chunks/thread per tile each for A and W).
    // A-row sources clamped in-bounds; pred=false zero-fills via src-size 0.
    const int ac0r = tid >> 2,           ac0k = (tid & 3) * 4;
    const int ac1r = (tid + 256) >> 2,   ac1k = ((tid + 256) & 3) * 4;
    const int wc0r = tid >> 5,           wc0n = (tid & 31) * 4;
    const int wc1r = (tid + 256) >> 5,   wc1n = ((tid + 256) & 31) * 4;
    const bool a0ok = block_row + ac0r < n;
    const bool a1ok = block_row + ac1r < n;
    const int a0row = a0ok ? block_row + ac0r : n - 1;   // clamped, never OOB
    const int a1row = a1ok ? block_row + ac1r : n - 1;

    auto load_tile = [&](int i, int s) {
        int k0 = i * 16;
        cpa16((unsigned)__cvta_generic_to_shared(&As[s][ac0r][ac0k]),
              A + (size_t)a0row * CH + k0 + ac0k, a0ok);
        cpa16((unsigned)__cvta_generic_to_shared(&As[s][ac1r][ac1k]),
              A + (size_t)a1row * CH + k0 + ac1k, a1ok);
        cpa16((unsigned)__cvta_generic_to_shared(&Ws[s][wc0r][wc0n]),
              W + (size_t)(k0 + wc0r) * CH + wc0n, true);
        cpa16((unsigned)__cvta_generic_to_shared(&Ws[s][wc1r][wc1n]),
              W + (size_t)(k0 + wc1r) * CH + wc1n, true);
        CP_COMMIT();
    };

    float acc[2][8][4];
#pragma unroll
    for (int mt = 0; mt < 2; mt++)
#pragma unroll
        for (int nt = 0; nt < 8; nt++)
#pragma unroll
            for (int r = 0; r < 4; r++) acc[mt][nt][r] = 0.0f;

    load_tile(0, 0);

#pragma unroll
    for (int i = 0; i < 8; i++) {
        const int s = i & 1;
        CP_WAIT0();
        __syncthreads();
        if (i + 1 < 8) load_tile(i + 1, (i + 1) & 1);  // overlaps compute below

#pragma unroll
        for (int ks = 0; ks < 2; ks++) {
            const int kk = ks * 8;
            unsigned ah[2][4], al[2][4];
#pragma unroll
            for (int mt = 0; mt < 2; mt++) {
                const int m = wm + mt * 16;
                float raw[4];
                raw[0] = As[s][m + gid][kk + tig];
                raw[1] = As[s][m + gid + 8][kk + tig];
                raw[2] = As[s][m + gid][kk + tig + 4];
                raw[3] = As[s][m + gid + 8][kk + tig + 4];
#pragma unroll
                for (int r = 0; r < 4; r++) {
                    float x = RELU ? fmaxf(raw[r], 0.0f) : raw[r];
                    float h = tf32_rna(x);
                    ah[mt][r] = __float_as_uint(h);
                    al[mt][r] = __float_as_uint(tf32_rna(x - h));
                }
            }
            unsigned bh[8][2], bl[8][2];
#pragma unroll
            for (int nt = 0; nt < 8; nt++) {
                const int nn = wn + nt * 8 + gid;
                float x0 = Ws[s][kk + tig][nn];
                float x1 = Ws[s][kk + tig + 4][nn];
                float h0 = tf32_rna(x0);
                float h1 = tf32_rna(x1);
                bh[nt][0] = __float_as_uint(h0);
                bh[nt][1] = __float_as_uint(h1);
                bl[nt][0] = __float_as_uint(tf32_rna(x0 - h0));
                bl[nt][1] = __float_as_uint(tf32_rna(x1 - h1));
            }
#pragma unroll
            for (int mt = 0; mt < 2; mt++)
#pragma unroll
                for (int nt = 0; nt < 8; nt++) {
                    mma_tf32(acc[mt][nt], ah[mt], bh[nt]);  // hi*hi
                    mma_tf32(acc[mt][nt], ah[mt], bl[nt]);  // hi*lo
                    mma_tf32(acc[mt][nt], al[mt], bh[nt]);  // lo*hi
                }
        }
        __syncthreads();   // all warps done with buffer s before refill
    }

    // Epilogue: c0,c1 at (row, 2*tig), (row, 2*tig+1); c2,c3 at row+8.
#pragma unroll
    for (int mt = 0; mt < 2; mt++) {
#pragma unroll
        for (int nt = 0; nt < 8; nt++) {
            int r0 = block_row + wm + mt * 16 + gid;
            int cb = wn + nt * 8 + 2 * tig;
            if (r0 < n)
                *(float2*)(C + (size_t)r0 * CH + cb) = make_float2(acc[mt][nt][0], acc[mt][nt][1]);
            if (r0 + 8 < n)
                *(float2*)(C + (size_t)(r0 + 8) * CH + cb) = make_float2(acc[mt][nt][2], acc[mt][nt][3]);
        }
    }
}

// ---------------------------------------------------------------------------
// (6,8) Pull aggregation: one warp per node, register accumulation.
//   out[i,:] = sum_{e:dst=i} h[src_e,:]*coef_e + h[i,:]*dinv^2 + b[:]
// ---------------------------------------------------------------------------
__global__ void __launch_bounds__(256)
gather_kernel(const float* __restrict__ h, const float* __restrict__ b,
              float* __restrict__ out, int n) {
    int node = (blockIdx.x * blockDim.x + threadIdx.x) >> 5;
    int lane = threadIdx.x & 31;
    if (node >= n) return;

    int start = g_row[node];
    int deg = g_deg[node];
    float di = g_dinv[node];
    float sl = di * di;

    float4 hv = ((const float4*)(h + (size_t)node * CH))[lane];
    float4 bv = ((const float4*)b)[lane];
    float4 acc;
    acc.x = fmaf(hv.x, sl, bv.x);
    acc.y = fmaf(hv.y, sl, bv.y);
    acc.z = fmaf(hv.z, sl, bv.z);
    acc.w = fmaf(hv.w, sl, bv.w);

    for (int j0 = 0; j0 < deg; j0 += 32) {
        int nn = min(32, deg - j0);
        int2 e = make_int2(0, 0);
        if (lane < nn) e = g_csr[start + j0 + lane];
#pragma unroll 8
        for (int k = 0; k < nn; k++) {
            int s = __shfl_sync(0xFFFFFFFFu, e.x, k);
            float c = __int_as_float(__shfl_sync(0xFFFFFFFFu, e.y, k));
            float4 v = ((const float4*)(h + (size_t)s * CH))[lane];
            acc.x = fmaf(v.x, c, acc.x);
            acc.y = fmaf(v.y, c, acc.y);
            acc.z = fmaf(v.z, c, acc.z);
            acc.w = fmaf(v.w, c, acc.w);
        }
    }
    ((float4*)(out + (size_t)node * CH))[lane] = acc;
}

// ---------------------------------------------------------------------------
// Launch. Order puts gemm layer-1 at position 4 (the ncu-profiled slot).
// ---------------------------------------------------------------------------
extern "C" void kernel_launch(void* const* d_in, const int* in_sizes, int n_in,
                              void* d_out, int out_size) {
    const float* x  = (const float*)d_in[0];
    const void*  ei = d_in[1];
    const float* W1 = (const float*)d_in[2];
    const float* b1 = (const float*)d_in[3];
    const float* W2 = (const float*)d_in[4];
    const float* b2 = (const float*)d_in[5];
    float*       out = (float*)d_out;

    const int N = in_sizes[0] / CH;
    const int E = in_sizes[1] / 2;

    float *hp = nullptr, *aggp = nullptr;
    cudaGetSymbolAddress((void**)&hp, g_h);
    cudaGetSymbolAddress((void**)&aggp, g_agg);

    const int T = 256;
    const int gemm_grid = (N + 127) / 128;
    const int edge_grid = (E + T - 1) / T;
    const int node_grid = (N + T - 1) / T;
    const int conv_grid = (2 * E + T - 1) / T;
    const int warp_grid = (N * 32 + T - 1) / T;

    init_detect_kernel<<<node_grid, T>>>((const unsigned int*)ei, 2 * E, N);   // 1
    convert_kernel<<<conv_grid, T>>>(ei, E);                                   // 2
    dinv_alloc_kernel<<<node_grid, T>>>(N);                                    // 3
    gemm_tf32_kernel<false><<<gemm_grid, T>>>(x, W1, hp, N);                   // 4 (profiled)
    csr_fill_kernel<<<edge_grid, T>>>(E);                                      // 5
    gather_kernel<<<warp_grid, T>>>(hp, b1, aggp, N);                          // 6
    gemm_tf32_kernel<true><<<gemm_grid, T>>>(aggp, W2, hp, N);                 // 7
    gather_kernel<<<warp_grid, T>>>(hp, b2, out, N);                           // 8
}

// round 10
// speedup vs baseline: 2.3849x; 1.0643x over previous
#include <cuda_runtime.h>
#include <cuda_bf16.h>
#include <cstdint>

// ---------------------------------------------------------------------------
// GCNEncoder: 2-layer GCN.
//   h1 = relu( Dinv (A+I) Dinv (x @ W1) + b1 )
//   out =      Dinv (A+I) Dinv (h1 @ W2) + b2
// N = 100000, E = 1600000, CH = 128.
// R10: bf16x3 mma.sync.m16n8k16 GEMM (operands pre-split to bf16 hi/lo tile
// images by producer kernels; whole-K smem residency) + CSR pull gather.
// NOTE: harness PTX target is sm_100 (no 'a') -> tcgen05 unavailable.
// ---------------------------------------------------------------------------

#define MAX_N 100000
#define MAX_E 1600000
#define CH 128
#define NT 782                       // ceil(100000/128) row tiles
#define TILE_ELEMS 16384             // 128x128 bf16 per tile image

__device__ alignas(16) float g_h[(size_t)MAX_N * CH];          // GEMM output
__device__ alignas(16) __nv_bfloat16 g_Ahi[(size_t)NT * TILE_ELEMS];
__device__ alignas(16) __nv_bfloat16 g_Alo[(size_t)NT * TILE_ELEMS];
__device__ alignas(16) __nv_bfloat16 g_W1hi[TILE_ELEMS];   // [n][k] transposed
__device__ alignas(16) __nv_bfloat16 g_W1lo[TILE_ELEMS];
__device__ alignas(16) __nv_bfloat16 g_W2hi[TILE_ELEMS];
__device__ alignas(16) __nv_bfloat16 g_W2lo[TILE_ELEMS];
__device__ float g_dinv[MAX_N];
__device__ int   g_deg[MAX_N];
__device__ int   g_row[MAX_N];
__device__ int   g_cur[MAX_N];
__device__ int   g_idx[2 * MAX_E];
__device__ int2  g_csr[MAX_E];
__device__ unsigned int g_or_hi;
__device__ unsigned int g_alloc;

// ---------------------------------------------------------------------------
// (1) init + dtype detection. int64 indices in [0,N) have zero high words.
// ---------------------------------------------------------------------------
__global__ void init_detect_kernel(const unsigned int* __restrict__ w,
                                   int nwords, int n) {
    int i = blockIdx.x * blockDim.x + threadIdx.x;
    if (i < n) g_deg[i] = 0;
    if (i == 0) { g_alloc = 0u; }
    if (blockIdx.x == 0) {
        unsigned int v = 0;
        for (int j = threadIdx.x; j < 1024; j += blockDim.x) {
            int idx = 2 * j + 1;
            if (idx < nwords) v |= w[idx];
        }
        for (int off = 16; off > 0; off >>= 1)
            v |= __shfl_down_sync(0xFFFFFFFFu, v, off);
        __shared__ unsigned int sv[8];
        if ((threadIdx.x & 31) == 0) sv[threadIdx.x >> 5] = v;
        __syncthreads();
        if (threadIdx.x == 0) {
            unsigned int r = 0;
            for (int wz = 0; wz < (int)(blockDim.x >> 5); wz++) r |= sv[wz];
            g_or_hi = r;
        }
    }
}

// (2) convert indices to int32 + count in-degrees (dst half).
__global__ void convert_kernel(const void* __restrict__ ei, int E) {
    int i = blockIdx.x * blockDim.x + threadIdx.x;
    if (i >= 2 * E) return;
    int v;
    if (g_or_hi == 0u) v = (int)((const long long*)ei)[i];
    else               v = ((const int*)ei)[i];
    g_idx[i] = v;
    if (i >= E) atomicAdd(&g_deg[v], 1);
}

// ---------------------------------------------------------------------------
// (3) Split inputs to bf16 hi/lo tile images (plain row-major layout).
// Blocks [0, nt): x tiles [128][128]. Block nt: W1, nt+1: W2 as [n][k].
// ---------------------------------------------------------------------------
__global__ void __launch_bounds__(256)
split_inputs_kernel(const float* __restrict__ x, const float* __restrict__ W1,
                    const float* __restrict__ W2, int n, int nt) {
    int b = blockIdx.x;
    int tid = threadIdx.x;
    if (b < nt) {
        size_t img = (size_t)b * TILE_ELEMS;
#pragma unroll
        for (int i = 0; i < 8; i++) {
            int chunk = tid + i * 256;            // 0..2047
            int r = chunk >> 4;                   // 0..127
            int c8 = (chunk & 15) * 8;            // 0..120 step 8
            int gr = b * 128 + r;
            if (gr >= n) continue;
            const float4* src = (const float4*)(x + (size_t)gr * CH + c8);
            float4 v0 = src[0], v1 = src[1];
            float vv[8] = {v0.x, v0.y, v0.z, v0.w, v1.x, v1.y, v1.z, v1.w};
            __nv_bfloat16 hi[8], lo[8];
#pragma unroll
            for (int j = 0; j < 8; j++) {
                hi[j] = __float2bfloat16(vv[j]);
                lo[j] = __float2bfloat16(vv[j] - __bfloat162float(hi[j]));
            }
            size_t off = img + r * 128 + c8;
            *(uint4*)(g_Ahi + off) = *(uint4*)hi;
            *(uint4*)(g_Alo + off) = *(uint4*)lo;
        }
    } else {
        const float* W = (b == nt) ? W1 : W2;
        __nv_bfloat16* dh = (b == nt) ? g_W1hi : g_W2hi;
        __nv_bfloat16* dl = (b == nt) ? g_W1lo : g_W2lo;
#pragma unroll
        for (int i = 0; i < 8; i++) {
            int chunk = tid + i * 256;
            int k = chunk >> 4;
            int n8 = (chunk & 15) * 8;
            const float4* src = (const float4*)(W + (size_t)k * CH + n8);
            float4 v0 = src[0], v1 = src[1];
            float vv[8] = {v0.x, v0.y, v0.z, v0.w, v1.x, v1.y, v1.z, v1.w};
#pragma unroll
            for (int j = 0; j < 8; j++) {
                __nv_bfloat16 h = __float2bfloat16(vv[j]);
                __nv_bfloat16 l = __float2bfloat16(vv[j] - __bfloat162float(h));
                dh[(n8 + j) * 128 + k] = h;       // B[n][k] = W[k][n]
                dl[(n8 + j) * 128 + k] = l;
            }
        }
    }
}

// ---------------------------------------------------------------------------
// (5) dinv + CSR row allocation (block scan + atomic base).
// ---------------------------------------------------------------------------
__global__ void __launch_bounds__(256)
dinv_alloc_kernel(int n) {
    int i = blockIdx.x * 256 + threadIdx.x;
    int lane = threadIdx.x & 31;
    int wid = threadIdx.x >> 5;
    int d = (i < n) ? g_deg[i] : 0;
    if (i < n) g_dinv[i] = rsqrtf((float)d + 1.0f);

    int v = d;
#pragma unroll
    for (int off = 1; off < 32; off <<= 1) {
        int t = __shfl_up_sync(0xFFFFFFFFu, v, off);
        if (lane >= off) v += t;
    }
    __shared__ int wsum[8];
    __shared__ int woff[8];
    __shared__ int base;
    if (lane == 31) wsum[wid] = v;
    __syncthreads();
    if (threadIdx.x == 0) {
        int run = 0;
#pragma unroll
        for (int w = 0; w < 8; w++) { woff[w] = run; run += wsum[w]; }
        base = (int)atomicAdd(&g_alloc, (unsigned int)run);
    }
    __syncthreads();
    if (i < n) {
        int start = base + woff[wid] + (v - d);
        g_row[i] = start;
        g_cur[i] = start;
    }
}

// (6) Fill CSR: (src, coef) per edge, grouped by dst.
__global__ void csr_fill_kernel(int E) {
    int e = blockIdx.x * blockDim.x + threadIdx.x;
    if (e >= E) return;
    int s = g_idx[e];
    int d = g_idx[E + e];
    float coef = g_dinv[s] * g_dinv[d];
    int pos = atomicAdd(&g_cur[d], 1);
    g_csr[pos] = make_int2(s, __float_as_int(coef));
}

// ---------------------------------------------------------------------------
// (4,8) GEMM: C[tile 128][128] = A_tile @ B^T via mma.sync m16n8k16 bf16,
// 3-term error compensation (hi*hi + hi*lo + lo*hi), fp32 accumulators.
// 256 threads, 8 warps as 4x2 -> 32x64 per warp. Whole K resident in smem.
// ---------------------------------------------------------------------------
__device__ __forceinline__ void mma_bf16(float* c, const unsigned* a, const unsigned* b) {
    asm volatile(
        "mma.sync.aligned.m16n8k16.row.col.f32.bf16.bf16.f32 "
        "{%0,%1,%2,%3}, {%4,%5,%6,%7}, {%8,%9}, {%0,%1,%2,%3};"
        : "+f"(c[0]), "+f"(c[1]), "+f"(c[2]), "+f"(c[3])
        : "r"(a[0]), "r"(a[1]), "r"(a[2]), "r"(a[3]), "r"(b[0]), "r"(b[1]));
}
__device__ __forceinline__ void cpa16(unsigned dst, const void* src) {
    asm volatile("cp.async.cg.shared.global [%0], [%1], 16;"
                 :: "r"(dst), "l"(src) : "memory");
}
#define CP_COMMIT() asm volatile("cp.async.commit_group;" ::: "memory")
#define CP_WAIT0()  asm volatile("cp.async.wait_group 0;" ::: "memory")

#define SROW_W 68                      // smem row stride in 32-bit words (136 bf16)
#define SROW_B 272                     // bytes per smem row
#define ARR_B  (128 * SROW_B)          // 34816 B per operand array
#define SMEM_T (4 * ARR_B)             // 139264 B total

template <int LAYER>
__global__ void __launch_bounds__(256, 1)
gemm_bf16_kernel(float* __restrict__ C, int n) {
    extern __shared__ char smem[];
    const int tid = threadIdx.x;
    const int lane = tid & 31;
    const int wid = tid >> 5;
    const int tile = blockIdx.x;
    const int block_row = tile * 128;
    const int wm = (wid & 3) * 32;
    const int wn = (wid >> 2) * 64;
    const int gid = lane >> 2;          // 0..7
    const int tig = lane & 3;           // 0..3

    // Bulk cp.async load of 4 pre-split images into padded smem.
    {
        unsigned sb;
        asm("{ .reg .u64 t; cvta.to.shared.u64 t, %1; cvt.u32.u64 %0, t; }"
            : "=r"(sb) : "l"(smem));
        const char* srcs[4] = {
            (const char*)(g_Ahi + (size_t)tile * TILE_ELEMS),
            (const char*)(g_Alo + (size_t)tile * TILE_ELEMS),
            (const char*)(LAYER == 1 ? g_W1hi : g_W2hi),
            (const char*)(LAYER == 1 ? g_W1lo : g_W2lo)};
#pragma unroll
        for (int p = 0; p < 4; p++)
#pragma unroll
            for (int i = 0; i < 8; i++) {
                int chunk = tid + i * 256;         // 0..2047
                int r = chunk >> 4;
                int c = (chunk & 15) * 16;          // byte offset in row
                cpa16(sb + p * ARR_B + r * SROW_B + c, srcs[p] + r * 256 + c);
            }
        CP_COMMIT();
        CP_WAIT0();
    }
    __syncthreads();

    const unsigned* sAh = (const unsigned*)(smem);
    const unsigned* sAl = (const unsigned*)(smem + ARR_B);
    const unsigned* sWh = (const unsigned*)(smem + 2 * ARR_B);
    const unsigned* sWl = (const unsigned*)(smem + 3 * ARR_B);

    float acc[2][8][4];
#pragma unroll
    for (int mt = 0; mt < 2; mt++)
#pragma unroll
        for (int nt = 0; nt < 8; nt++)
#pragma unroll
            for (int r = 0; r < 4; r++) acc[mt][nt][r] = 0.0f;

#pragma unroll
    for (int ks = 0; ks < 8; ks++) {
        const int kw = ks * 8 + tig;          // word offset within row
        unsigned ah[2][4], al[2][4];
#pragma unroll
        for (int mt = 0; mt < 2; mt++) {
            const int m0 = (wm + mt * 16 + gid) * SROW_W;
            const int m8 = m0 + 8 * SROW_W;
            ah[mt][0] = sAh[m0 + kw];
            ah[mt][1] = sAh[m8 + kw];
            ah[mt][2] = sAh[m0 + kw + 4];
            ah[mt][3] = sAh[m8 + kw + 4];
            al[mt][0] = sAl[m0 + kw];
            al[mt][1] = sAl[m8 + kw];
            al[mt][2] = sAl[m0 + kw + 4];
            al[mt][3] = sAl[m8 + kw + 4];
        }
        unsigned bh[8][2], bl[8][2];
#pragma unroll
        for (int nt = 0; nt < 8; nt++) {
            const int nn = (wn + nt * 8 + gid) * SROW_W;
            bh[nt][0] = sWh[nn + kw];
            bh[nt][1] = sWh[nn + kw + 4];
            bl[nt][0] = sWl[nn + kw];
            bl[nt][1] = sWl[nn + kw + 4];
        }
#pragma unroll
        for (int mt = 0; mt < 2; mt++)
#pragma unroll
            for (int nt = 0; nt < 8; nt++) {
                mma_bf16(acc[mt][nt], ah[mt], bh[nt]);   // hi*hi
                mma_bf16(acc[mt][nt], ah[mt], bl[nt]);   // hi*lo
                mma_bf16(acc[mt][nt], al[mt], bh[nt]);   // lo*hi
            }
    }

    // Epilogue: c0,c1 -> (row, 2tig/2tig+1); c2,c3 -> row+8.
#pragma unroll
    for (int mt = 0; mt < 2; mt++) {
#pragma unroll
        for (int nt = 0; nt < 8; nt++) {
            int r0 = block_row + wm + mt * 16 + gid;
            int cb = wn + nt * 8 + 2 * tig;
            if (r0 < n)
                *(float2*)(C + (size_t)r0 * CH + cb) = make_float2(acc[mt][nt][0], acc[mt][nt][1]);
            if (r0 + 8 < n)
                *(float2*)(C + (size_t)(r0 + 8) * CH + cb) = make_float2(acc[mt][nt][2], acc[mt][nt][3]);
        }
    }
}

// ---------------------------------------------------------------------------
// (7,9) Pull aggregation: one warp per node, register accumulation.
// SPLIT=true: relu + write bf16 hi/lo tile images (feeds GEMM2).
// SPLIT=false: write fp32 rows (final output).
// ---------------------------------------------------------------------------
template <bool SPLIT>
__global__ void __launch_bounds__(256)
gather_kernel(const float* __restrict__ h, const float* __restrict__ b,
              float* __restrict__ out, int n) {
    int node = (blockIdx.x * blockDim.x + threadIdx.x) >> 5;
    int lane = threadIdx.x & 31;
    if (node >= n) return;

    int start = g_row[node];
    int deg = g_deg[node];
    float di = g_dinv[node];
    float sl = di * di;

    float4 hv = ((const float4*)(h + (size_t)node * CH))[lane];
    float4 bv = ((const float4*)b)[lane];
    float4 acc;
    acc.x = fmaf(hv.x, sl, bv.x);
    acc.y = fmaf(hv.y, sl, bv.y);
    acc.z = fmaf(hv.z, sl, bv.z);
    acc.w = fmaf(hv.w, sl, bv.w);

    for (int j0 = 0; j0 < deg; j0 += 32) {
        int nn = min(32, deg - j0);
        int2 e = make_int2(0, 0);
        if (lane < nn) e = g_csr[start + j0 + lane];
#pragma unroll 8
        for (int k = 0; k < nn; k++) {
            int s = __shfl_sync(0xFFFFFFFFu, e.x, k);
            float c = __int_as_float(__shfl_sync(0xFFFFFFFFu, e.y, k));
            float4 v = ((const float4*)(h + (size_t)s * CH))[lane];
            acc.x = fmaf(v.x, c, acc.x);
            acc.y = fmaf(v.y, c, acc.y);
            acc.z = fmaf(v.z, c, acc.z);
            acc.w = fmaf(v.w, c, acc.w);
        }
    }

    if (SPLIT) {
        float vv[4] = {fmaxf(acc.x, 0.f), fmaxf(acc.y, 0.f),
                       fmaxf(acc.z, 0.f), fmaxf(acc.w, 0.f)};
        __nv_bfloat16 hi[4], lo[4];
#pragma unroll
        for (int j = 0; j < 4; j++) {
            hi[j] = __float2bfloat16(vv[j]);
            lo[j] = __float2bfloat16(vv[j] - __bfloat162float(hi[j]));
        }
        size_t off = (size_t)(node >> 7) * TILE_ELEMS + (node & 127) * 128 + lane * 4;
        *(uint2*)(g_Ahi + off) = *(uint2*)hi;
        *(uint2*)(g_Alo + off) = *(uint2*)lo;
    } else {
        ((float4*)(out + (size_t)node * CH))[lane] = acc;
    }
}

// ---------------------------------------------------------------------------
// Launch. Slot 4 (ncu-profiled) = gemm layer 1.
// ---------------------------------------------------------------------------
extern "C" void kernel_launch(void* const* d_in, const int* in_sizes, int n_in,
                              void* d_out, int out_size) {
    const float* x  = (const float*)d_in[0];
    const void*  ei = d_in[1];
    const float* W1 = (const float*)d_in[2];
    const float* b1 = (const float*)d_in[3];
    const float* W2 = (const float*)d_in[4];
    const float* b2 = (const float*)d_in[5];
    float*       out = (float*)d_out;

    const int N = in_sizes[0] / CH;
    const int E = in_sizes[1] / 2;
    const int nt = (N + 127) / 128;

    float* hp = nullptr;
    cudaGetSymbolAddress((void**)&hp, g_h);

    cudaFuncSetAttribute(gemm_bf16_kernel<1>,
                         cudaFuncAttributeMaxDynamicSharedMemorySize, SMEM_T);
    cudaFuncSetAttribute(gemm_bf16_kernel<2>,
                         cudaFuncAttributeMaxDynamicSharedMemorySize, SMEM_T);

    const int T = 256;
    const int edge_grid = (E + T - 1) / T;
    const int node_grid = (N + T - 1) / T;
    const int conv_grid = (2 * E + T - 1) / T;
    const int warp_grid = (N * 32 + T - 1) / T;

    init_detect_kernel<<<node_grid, T>>>((const unsigned int*)ei, 2 * E, N); // 1
    convert_kernel<<<conv_grid, T>>>(ei, E);                                 // 2
    split_inputs_kernel<<<nt + 2, T>>>(x, W1, W2, N, nt);                    // 3
    gemm_bf16_kernel<1><<<nt, T, SMEM_T>>>(hp, N);                           // 4 (profiled)
    dinv_alloc_kernel<<<node_grid, T>>>(N);                                  // 5
    csr_fill_kernel<<<edge_grid, T>>>(E);                                    // 6
    gather_kernel<true><<<warp_grid, T>>>(hp, b1, nullptr, N);               // 7
    gemm_bf16_kernel<2><<<nt, T, SMEM_T>>>(hp, N);                           // 8
    gather_kernel<false><<<warp_grid, T>>>(hp, b2, out, N);                  // 9
}

// round 11
// speedup vs baseline: 2.5135x; 1.0539x over previous
#include <cuda_runtime.h>
#include <cuda_bf16.h>
#include <cstdint>

// ---------------------------------------------------------------------------
// GCNEncoder: 2-layer GCN.
//   h1 = relu( Dinv (A+I) Dinv (x @ W1) + b1 )
//   out =      Dinv (A+I) Dinv (h1 @ W2) + b2
// N = 100000, E = 1600000, CH = 128.
// R11: bf16x3 mma.sync m16n8k16 GEMM, M-tile=64 (2 CTAs/SM), x-split fused
// into GEMM1 A-load. A hi/lo images row-major [node][128]. CSR pull gather.
// (tcgen05 unavailable: harness compiles PTX at sm_100, no 'a'.)
// ---------------------------------------------------------------------------

#define MAX_N 100000
#define AROWS 100096                 // padded row count for images
#define MAX_E 1600000
#define CH 128

__device__ alignas(16) float g_h[(size_t)MAX_N * CH];          // GEMM output
__device__ alignas(16) __nv_bfloat16 g_Ahi[(size_t)AROWS * CH];
__device__ alignas(16) __nv_bfloat16 g_Alo[(size_t)AROWS * CH];
__device__ alignas(16) __nv_bfloat16 g_W1hi[CH * CH];   // [n][k] transposed
__device__ alignas(16) __nv_bfloat16 g_W1lo[CH * CH];
__device__ alignas(16) __nv_bfloat16 g_W2hi[CH * CH];
__device__ alignas(16) __nv_bfloat16 g_W2lo[CH * CH];
__device__ float g_dinv[MAX_N];
__device__ int   g_deg[MAX_N];
__device__ int   g_row[MAX_N];
__device__ int   g_cur[MAX_N];
__device__ int   g_idx[2 * MAX_E];
__device__ int2  g_csr[MAX_E];
__device__ unsigned int g_or_hi;
__device__ unsigned int g_alloc;

// ---------------------------------------------------------------------------
// (1) init + dtype detection. int64 indices in [0,N) have zero high words.
// ---------------------------------------------------------------------------
__global__ void init_detect_kernel(const unsigned int* __restrict__ w,
                                   int nwords, int n) {
    int i = blockIdx.x * blockDim.x + threadIdx.x;
    if (i < n) g_deg[i] = 0;
    if (i == 0) { g_alloc = 0u; }
    if (blockIdx.x == 0) {
        unsigned int v = 0;
        for (int j = threadIdx.x; j < 1024; j += blockDim.x) {
            int idx = 2 * j + 1;
            if (idx < nwords) v |= w[idx];
        }
        for (int off = 16; off > 0; off >>= 1)
            v |= __shfl_down_sync(0xFFFFFFFFu, v, off);
        __shared__ unsigned int sv[8];
        if ((threadIdx.x & 31) == 0) sv[threadIdx.x >> 5] = v;
        __syncthreads();
        if (threadIdx.x == 0) {
            unsigned int r = 0;
            for (int wz = 0; wz < (int)(blockDim.x >> 5); wz++) r |= sv[wz];
            g_or_hi = r;
        }
    }
}

// (2) convert indices to int32 + count in-degrees (dst half).
__global__ void convert_kernel(const void* __restrict__ ei, int E) {
    int i = blockIdx.x * blockDim.x + threadIdx.x;
    if (i >= 2 * E) return;
    int v;
    if (g_or_hi == 0u) v = (int)((const long long*)ei)[i];
    else               v = ((const int*)ei)[i];
    g_idx[i] = v;
    if (i >= E) atomicAdd(&g_deg[v], 1);
}

// ---------------------------------------------------------------------------
// (3) Split W1/W2 to bf16 hi/lo as B[n][k] (block 0 = W1, block 1 = W2).
// ---------------------------------------------------------------------------
__global__ void __launch_bounds__(256)
split_w_kernel(const float* __restrict__ W1, const float* __restrict__ W2) {
    int b = blockIdx.x;
    int tid = threadIdx.x;
    const float* W = (b == 0) ? W1 : W2;
    __nv_bfloat16* dh = (b == 0) ? g_W1hi : g_W2hi;
    __nv_bfloat16* dl = (b == 0) ? g_W1lo : g_W2lo;
#pragma unroll
    for (int i = 0; i < 8; i++) {
        int chunk = tid + i * 256;        // 0..2047
        int k = chunk >> 4;
        int n8 = (chunk & 15) * 8;
        const float4* src = (const float4*)(W + (size_t)k * CH + n8);
        float4 v0 = src[0], v1 = src[1];
        float vv[8] = {v0.x, v0.y, v0.z, v0.w, v1.x, v1.y, v1.z, v1.w};
#pragma unroll
        for (int j = 0; j < 8; j++) {
            __nv_bfloat16 h = __float2bfloat16(vv[j]);
            __nv_bfloat16 l = __float2bfloat16(vv[j] - __bfloat162float(h));
            dh[(n8 + j) * CH + k] = h;    // B[n][k] = W[k][n]
            dl[(n8 + j) * CH + k] = l;
        }
    }
}

// ---------------------------------------------------------------------------
// (5) dinv + CSR row allocation (block scan + atomic base).
// ---------------------------------------------------------------------------
__global__ void __launch_bounds__(256)
dinv_alloc_kernel(int n) {
    int i = blockIdx.x * 256 + threadIdx.x;
    int lane = threadIdx.x & 31;
    int wid = threadIdx.x >> 5;
    int d = (i < n) ? g_deg[i] : 0;
    if (i < n) g_dinv[i] = rsqrtf((float)d + 1.0f);

    int v = d;
#pragma unroll
    for (int off = 1; off < 32; off <<= 1) {
        int t = __shfl_up_sync(0xFFFFFFFFu, v, off);
        if (lane >= off) v += t;
    }
    __shared__ int wsum[8];
    __shared__ int woff[8];
    __shared__ int base;
    if (lane == 31) wsum[wid] = v;
    __syncthreads();
    if (threadIdx.x == 0) {
        int run = 0;
#pragma unroll
        for (int w = 0; w < 8; w++) { woff[w] = run; run += wsum[w]; }
        base = (int)atomicAdd(&g_alloc, (unsigned int)run);
    }
    __syncthreads();
    if (i < n) {
        int start = base + woff[wid] + (v - d);
        g_row[i] = start;
        g_cur[i] = start;
    }
}

// (6) Fill CSR: (src, coef) per edge, grouped by dst.
__global__ void csr_fill_kernel(int E) {
    int e = blockIdx.x * blockDim.x + threadIdx.x;
    if (e >= E) return;
    int s = g_idx[e];
    int d = g_idx[E + e];
    float coef = g_dinv[s] * g_dinv[d];
    int pos = atomicAdd(&g_cur[d], 1);
    g_csr[pos] = make_int2(s, __float_as_int(coef));
}

// ---------------------------------------------------------------------------
// (4,8) GEMM: C[64-row tile][128] = A @ B^T via mma.sync m16n8k16 bf16,
// 3-term compensation. 256 threads, 8 warps as 4x2 -> 16x64 per warp.
// LAYER 1: A loaded fp32 from x and split in the load phase (no pre-pass).
// LAYER 2: A hi/lo cp.async'd from row-major images (written by gather).
// ---------------------------------------------------------------------------
__device__ __forceinline__ void mma_bf16(float* c, const unsigned* a, const unsigned* b) {
    asm volatile(
        "mma.sync.aligned.m16n8k16.row.col.f32.bf16.bf16.f32 "
        "{%0,%1,%2,%3}, {%4,%5,%6,%7}, {%8,%9}, {%0,%1,%2,%3};"
        : "+f"(c[0]), "+f"(c[1]), "+f"(c[2]), "+f"(c[3])
        : "r"(a[0]), "r"(a[1]), "r"(a[2]), "r"(a[3]), "r"(b[0]), "r"(b[1]));
}
__device__ __forceinline__ void cpa16p(unsigned dst, const void* src, bool p) {
    int sz = p ? 16 : 0;
    asm volatile("cp.async.cg.shared.global [%0], [%1], 16, %2;"
                 :: "r"(dst), "l"(src), "r"(sz) : "memory");
}
#define CP_COMMIT() asm volatile("cp.async.commit_group;" ::: "memory")
#define CP_WAIT0()  asm volatile("cp.async.wait_group 0;" ::: "memory")

#define SROW_W 68                      // smem row stride: 68 words = 136 bf16
#define SROW_B 272
#define A_B  (64 * SROW_B)             // 17408 B per A array (64 rows)
#define W_B  (128 * SROW_B)            // 34816 B per W array
#define SM_AH 0
#define SM_AL A_B
#define SM_WH (2 * A_B)
#define SM_WL (2 * A_B + W_B)
#define SMEM_T (2 * A_B + 2 * W_B)     // 104448 B

template <int LAYER>
__global__ void __launch_bounds__(256)
gemm_bf16_kernel(const float* __restrict__ X, float* __restrict__ C, int n) {
    extern __shared__ char smem[];
    const int tid = threadIdx.x;
    const int lane = tid & 31;
    const int wid = tid >> 5;
    const int block_row = blockIdx.x * 64;
    const int wm = (wid & 3) * 16;
    const int wn = (wid >> 2) * 64;
    const int gid = lane >> 2;          // 0..7
    const int tig = lane & 3;           // 0..3

    unsigned sb;
    asm("{ .reg .u64 t; cvta.to.shared.u64 t, %1; cvt.u32.u64 %0, t; }"
        : "=r"(sb) : "l"(smem));

    // W hi/lo via cp.async (128 rows x 256 B each).
    const char* wh = (const char*)(LAYER == 1 ? g_W1hi : g_W2hi);
    const char* wl = (const char*)(LAYER == 1 ? g_W1lo : g_W2lo);
#pragma unroll
    for (int i = 0; i < 8; i++) {
        int chunk = tid + i * 256;          // 0..2047
        int r = chunk >> 4;
        int cB = (chunk & 15) * 16;
        cpa16p(sb + SM_WH + r * SROW_B + cB, wh + r * 256 + cB, true);
        cpa16p(sb + SM_WL + r * SROW_B + cB, wl + r * 256 + cB, true);
    }

    if (LAYER == 1) {
        // A: load fp32 rows of x, split to bf16 hi/lo in registers, STS.
        __nv_bfloat16* sah = (__nv_bfloat16*)(smem + SM_AH);
        __nv_bfloat16* sal = (__nv_bfloat16*)(smem + SM_AL);
#pragma unroll
        for (int i = 0; i < 4; i++) {
            int chunk = tid + i * 256;      // 0..1023
            int r = chunk >> 4;             // 0..63
            int c8 = (chunk & 15) * 8;
            int gr = block_row + r;
            float4 v0 = make_float4(0.f, 0.f, 0.f, 0.f), v1 = v0;
            if (gr < n) {
                const float4* src = (const float4*)(X + (size_t)gr * CH + c8);
                v0 = src[0];
                v1 = src[1];
            }
            float vv[8] = {v0.x, v0.y, v0.z, v0.w, v1.x, v1.y, v1.z, v1.w};
            __nv_bfloat16 hi[8], lo[8];
#pragma unroll
            for (int j = 0; j < 8; j++) {
                hi[j] = __float2bfloat16(vv[j]);
                lo[j] = __float2bfloat16(vv[j] - __bfloat162float(hi[j]));
            }
            *(uint4*)(sah + r * 136 + c8) = *(uint4*)hi;
            *(uint4*)(sal + r * 136 + c8) = *(uint4*)lo;
        }
    } else {
        // A hi/lo via cp.async from row-major images (64 rows x 256 B).
#pragma unroll
        for (int i = 0; i < 4; i++) {
            int chunk = tid + i * 256;      // 0..1023
            int r = chunk >> 4;             // 0..63
            int cB = (chunk & 15) * 16;
            int gr = block_row + r;
            bool ok = gr < n;
            int srow = ok ? gr : (n - 1);   // clamped, never OOB
            cpa16p(sb + SM_AH + r * SROW_B + cB, (const char*)g_Ahi + (size_t)srow * 256 + cB, ok);
            cpa16p(sb + SM_AL + r * SROW_B + cB, (const char*)g_Alo + (size_t)srow * 256 + cB, ok);
        }
    }
    CP_COMMIT();
    CP_WAIT0();
    __syncthreads();

    const unsigned* sAh = (const unsigned*)(smem + SM_AH);
    const unsigned* sAl = (const unsigned*)(smem + SM_AL);
    const unsigned* sWh = (const unsigned*)(smem + SM_WH);
    const unsigned* sWl = (const unsigned*)(smem + SM_WL);

    float acc[8][4];
#pragma unroll
    for (int nt = 0; nt < 8; nt++)
#pragma unroll
        for (int r = 0; r < 4; r++) acc[nt][r] = 0.0f;

#pragma unroll
    for (int ks = 0; ks < 8; ks++) {
        const int kw = ks * 8 + tig;
        unsigned ah[4], al[4];
        {
            const int m0 = (wm + gid) * SROW_W;
            const int m8 = m0 + 8 * SROW_W;
            ah[0] = sAh[m0 + kw];
            ah[1] = sAh[m8 + kw];
            ah[2] = sAh[m0 + kw + 4];
            ah[3] = sAh[m8 + kw + 4];
            al[0] = sAl[m0 + kw];
            al[1] = sAl[m8 + kw];
            al[2] = sAl[m0 + kw + 4];
            al[3] = sAl[m8 + kw + 4];
        }
        unsigned bh[8][2], bl[8][2];
#pragma unroll
        for (int nt = 0; nt < 8; nt++) {
            const int nn = (wn + nt * 8 + gid) * SROW_W;
            bh[nt][0] = sWh[nn + kw];
            bh[nt][1] = sWh[nn + kw + 4];
            bl[nt][0] = sWl[nn + kw];
            bl[nt][1] = sWl[nn + kw + 4];
        }
#pragma unroll
        for (int nt = 0; nt < 8; nt++) {
            mma_bf16(acc[nt], ah, bh[nt]);   // hi*hi
            mma_bf16(acc[nt], ah, bl[nt]);   // hi*lo
            mma_bf16(acc[nt], al, bh[nt]);   // lo*hi
        }
    }

    // Epilogue: c0,c1 -> (row, 2tig/2tig+1); c2,c3 -> row+8.
#pragma unroll
    for (int nt = 0; nt < 8; nt++) {
        int r0 = block_row + wm + gid;
        int cb = wn + nt * 8 + 2 * tig;
        if (r0 < n)
            *(float2*)(C + (size_t)r0 * CH + cb) = make_float2(acc[nt][0], acc[nt][1]);
        if (r0 + 8 < n)
            *(float2*)(C + (size_t)(r0 + 8) * CH + cb) = make_float2(acc[nt][2], acc[nt][3]);
    }
}

// ---------------------------------------------------------------------------
// (7,9) Pull aggregation: one warp per node, register accumulation.
// SPLIT=true: relu + write bf16 hi/lo rows (feeds GEMM2).
// SPLIT=false: write fp32 rows (final output).
// ---------------------------------------------------------------------------
template <bool SPLIT>
__global__ void __launch_bounds__(256)
gather_kernel(const float* __restrict__ h, const float* __restrict__ b,
              float* __restrict__ out, int n) {
    int node = (blockIdx.x * blockDim.x + threadIdx.x) >> 5;
    int lane = threadIdx.x & 31;
    if (node >= n) return;

    int start = g_row[node];
    int deg = g_deg[node];
    float di = g_dinv[node];
    float sl = di * di;

    float4 hv = ((const float4*)(h + (size_t)node * CH))[lane];
    float4 bv = ((const float4*)b)[lane];
    float4 acc;
    acc.x = fmaf(hv.x, sl, bv.x);
    acc.y = fmaf(hv.y, sl, bv.y);
    acc.z = fmaf(hv.z, sl, bv.z);
    acc.w = fmaf(hv.w, sl, bv.w);

    for (int j0 = 0; j0 < deg; j0 += 32) {
        int nn = min(32, deg - j0);
        int2 e = make_int2(0, 0);
        if (lane < nn) e = g_csr[start + j0 + lane];
#pragma unroll 8
        for (int k = 0; k < nn; k++) {
            int s = __shfl_sync(0xFFFFFFFFu, e.x, k);
            float c = __int_as_float(__shfl_sync(0xFFFFFFFFu, e.y, k));
            float4 v = ((const float4*)(h + (size_t)s * CH))[lane];
            acc.x = fmaf(v.x, c, acc.x);
            acc.y = fmaf(v.y, c, acc.y);
            acc.z = fmaf(v.z, c, acc.z);
            acc.w = fmaf(v.w, c, acc.w);
        }
    }

    if (SPLIT) {
        float vv[4] = {fmaxf(acc.x, 0.f), fmaxf(acc.y, 0.f),
                       fmaxf(acc.z, 0.f), fmaxf(acc.w, 0.f)};
        __nv_bfloat16 hi[4], lo[4];
#pragma unroll
        for (int j = 0; j < 4; j++) {
            hi[j] = __float2bfloat16(vv[j]);
            lo[j] = __float2bfloat16(vv[j] - __bfloat162float(hi[j]));
        }
        size_t off = (size_t)node * CH + lane * 4;
        *(uint2*)(g_Ahi + off) = *(uint2*)hi;
        *(uint2*)(g_Alo + off) = *(uint2*)lo;
    } else {
        ((float4*)(out + (size_t)node * CH))[lane] = acc;
    }
}

// ---------------------------------------------------------------------------
// Launch. Slot 4 (ncu-profiled) = gemm layer 1.
// ---------------------------------------------------------------------------
extern "C" void kernel_launch(void* const* d_in, const int* in_sizes, int n_in,
                              void* d_out, int out_size) {
    const float* x  = (const float*)d_in[0];
    const void*  ei = d_in[1];
    const float* W1 = (const float*)d_in[2];
    const float* b1 = (const float*)d_in[3];
    const float* W2 = (const float*)d_in[4];
    const float* b2 = (const float*)d_in[5];
    float*       out = (float*)d_out;

    const int N = in_sizes[0] / CH;
    const int E = in_sizes[1] / 2;
    const int nt64 = (N + 63) / 64;

    float* hp = nullptr;
    cudaGetSymbolAddress((void**)&hp, g_h);

    cudaFuncSetAttribute(gemm_bf16_kernel<1>,
                         cudaFuncAttributeMaxDynamicSharedMemorySize, SMEM_T);
    cudaFuncSetAttribute(gemm_bf16_kernel<2>,
                         cudaFuncAttributeMaxDynamicSharedMemorySize, SMEM_T);

    const int T = 256;
    const int edge_grid = (E + T - 1) / T;
    const int node_grid = (N + T - 1) / T;
    const int conv_grid = (2 * E + T - 1) / T;
    const int warp_grid = (N * 32 + T - 1) / T;

    init_detect_kernel<<<node_grid, T>>>((const unsigned int*)ei, 2 * E, N); // 1
    convert_kernel<<<conv_grid, T>>>(ei, E);                                 // 2
    split_w_kernel<<<2, T>>>(W1, W2);                                        // 3
    gemm_bf16_kernel<1><<<nt64, T, SMEM_T>>>(x, hp, N);                      // 4 (profiled)
    dinv_alloc_kernel<<<node_grid, T>>>(N);                                  // 5
    csr_fill_kernel<<<edge_grid, T>>>(E);                                    // 6
    gather_kernel<true><<<warp_grid, T>>>(hp, b1, nullptr, N);               // 7
    gemm_bf16_kernel<2><<<nt64, T, SMEM_T>>>(nullptr, hp, N);                // 8
    gather_kernel<false><<<warp_grid, T>>>(hp, b2, out, N);                  // 9
}